// round 1
// baseline (speedup 1.0000x reference)
#include <cuda_runtime.h>
#include <mma.h>

using namespace nvcuda;

#define B_NUM 4
#define CNUM  256
#define HWN   4096
#define NH    4
#define HD    64

// ---------------- scratch (device globals; allocation-free rule) ----------
__device__ float g_scale[B_NUM * CNUM];
__device__ float g_bias [B_NUM * CNUM];
__device__ float g_q [B_NUM * NH * HWN * HD];
__device__ float g_k [B_NUM * NH * HWN * HD];
__device__ float g_v [B_NUM * NH * HWN * HD];
__device__ float g_ao[B_NUM * HWN * CNUM];   // attention out, [b][p][c]

// ---------------- fast exp on FMA pipe (avoid MUFU bottleneck) ------------
__device__ __forceinline__ float fast_exp(float x) {
    x = fminf(fmaxf(x, -60.0f), 50.0f);
    float t = x * 1.4426950408889634f;       // x * log2(e)
    int   n = __float2int_rn(t);
    float f = t - (float)n;                  // f in [-0.5, 0.5]
    float p = 0.0013333558f;
    p = fmaf(p, f, 0.0096181291f);
    p = fmaf(p, f, 0.0555041087f);
    p = fmaf(p, f, 0.2402265069f);
    p = fmaf(p, f, 0.6931471806f);
    p = fmaf(p, f, 1.0f);
    return __int_as_float(__float_as_int(p) + (n << 23));
}

// ---------------- kernel 1: groupnorm stats -> per-(b,c) scale/bias -------
__global__ void gn_stats_kernel(const float* __restrict__ x,
                                const float* __restrict__ gamma,
                                const float* __restrict__ beta) {
    int bg = blockIdx.x;            // 32 blocks: b*8+g
    int b = bg >> 3, g = bg & 7;
    const float* base = x + ((size_t)(b * CNUM + g * 32)) * HWN; // 32ch contiguous
    const int N = 32 * HWN;
    float s = 0.f, s2 = 0.f;
    for (int i = threadIdx.x; i < N; i += 256) {
        float v = base[i];
        s += v; s2 += v * v;
    }
    __shared__ float r1[256], r2[256];
    r1[threadIdx.x] = s; r2[threadIdx.x] = s2;
    __syncthreads();
    for (int off = 128; off > 0; off >>= 1) {
        if (threadIdx.x < off) {
            r1[threadIdx.x] += r1[threadIdx.x + off];
            r2[threadIdx.x] += r2[threadIdx.x + off];
        }
        __syncthreads();
    }
    __shared__ float mean_s, rstd_s;
    if (threadIdx.x == 0) {
        float mean = r1[0] / (float)N;
        float var  = r2[0] / (float)N - mean * mean;
        mean_s = mean;
        rstd_s = rsqrtf(var + 1e-5f);
    }
    __syncthreads();
    if (threadIdx.x < 32) {
        int c = g * 32 + threadIdx.x;
        float sc = rstd_s * gamma[c];
        g_scale[b * CNUM + c] = sc;
        g_bias [b * CNUM + c] = beta[c] - mean_s * sc;
    }
}

// ---------------- kernel 2: fused GN + QKV GEMM (tf32 wmma) ----------------
// out[p, o] = sum_c h[p,c] * w_qkv[o,c];  scatter into g_q/g_k/g_v [b][h][p][d]
__global__ __launch_bounds__(128) void qkv_kernel(const float* __restrict__ x,
                                                  const float* __restrict__ wqkv,
                                                  const float* __restrict__ bqkv) {
    __shared__ float sm[4480];
    float* As = sm;          // A col-major: As[k*68 + m], k<32, m<64
    float* Bs = sm + 2176;   // B: Bs[n*36 + k], n<64, k<32 (col_major frag)
    int nt = blockIdx.x;     // 0..11  (o tile)
    int mt = blockIdx.y;     // 0..255 (pixel tile)
    int p0 = mt * 64;
    int b  = p0 >> 12;
    int hw0 = p0 & (HWN - 1);
    int o0 = nt * 64;
    int t = threadIdx.x, w = t >> 5;
    int wm = w & 1, wn = w >> 1;

    wmma::fragment<wmma::accumulator, 16, 16, 8, float> acc[2][2];
    #pragma unroll
    for (int i = 0; i < 2; i++)
        #pragma unroll
        for (int j = 0; j < 2; j++) wmma::fill_fragment(acc[i][j], 0.0f);

    for (int kt = 0; kt < 8; kt++) {
        int c0 = kt * 32;
        __syncthreads();
        #pragma unroll
        for (int i = 0; i < 16; i++) {               // A: 64m x 32k
            int e = i * 128 + t;
            int m = e & 63, k = e >> 6;
            int c = c0 + k;
            float v = fmaf(x[(((size_t)(b * CNUM + c)) << 12) + hw0 + m],
                           g_scale[b * CNUM + c], g_bias[b * CNUM + c]);
            As[k * 68 + m] = wmma::__float_to_tf32(v);
        }
        #pragma unroll
        for (int i = 0; i < 16; i++) {               // B: 64n x 32k
            int e = i * 128 + t;
            int k = e & 31, n = e >> 5;
            Bs[n * 36 + k] = wmma::__float_to_tf32(wqkv[(size_t)(o0 + n) * CNUM + c0 + k]);
        }
        __syncthreads();
        #pragma unroll
        for (int kk = 0; kk < 32; kk += 8) {
            wmma::fragment<wmma::matrix_a, 16, 16, 8, wmma::precision::tf32, wmma::col_major> a[2];
            wmma::fragment<wmma::matrix_b, 16, 16, 8, wmma::precision::tf32, wmma::col_major> bb[2];
            #pragma unroll
            for (int i = 0; i < 2; i++)
                wmma::load_matrix_sync(a[i], As + kk * 68 + (wm * 32 + i * 16), 68);
            #pragma unroll
            for (int j = 0; j < 2; j++)
                wmma::load_matrix_sync(bb[j], Bs + (wn * 32 + j * 16) * 36 + kk, 36);
            #pragma unroll
            for (int i = 0; i < 2; i++)
                #pragma unroll
                for (int j = 0; j < 2; j++)
                    wmma::mma_sync(acc[i][j], a[i], bb[j], acc[i][j]);
        }
    }
    __syncthreads();
    float* Cs = sm;                                  // 64 x 68
    #pragma unroll
    for (int i = 0; i < 2; i++)
        #pragma unroll
        for (int j = 0; j < 2; j++)
            wmma::store_matrix_sync(Cs + (wm * 32 + i * 16) * 68 + (wn * 32 + j * 16),
                                    acc[i][j], 68, wmma::mem_row_major);
    __syncthreads();
    int which = o0 >> 8;                // 0=q,1=k,2=v (tile never crosses)
    int head  = (o0 >> 6) & 3;
    float* dst = (which == 0) ? g_q : (which == 1) ? g_k : g_v;
    #pragma unroll
    for (int i = 0; i < 32; i++) {
        int e = i * 128 + t;
        int n = e & 63, m = e >> 6;
        float v = Cs[m * 68 + n] + bqkv[o0 + n];
        dst[(((size_t)((b * NH + head) * HWN + hw0 + m)) << 6) + n] = v;
    }
}

// ---------------- kernel 3: attention (flash-style, no-max softmax) --------
// grid (32, 16): 32 query tiles of 128, 16 batch-heads. 256 threads.
__global__ __launch_bounds__(256) void attn_kernel() {
    extern __shared__ float dsm[];
    float* Qs = dsm;                 // [128][68]
    float* Ks = dsm + 8704;          // [64][68]
    float* Vs = dsm + 13056;         // [64][68]
    float* Ss = dsm + 17408;         // [128][68]  (S, then P, then O)
    __shared__ float den[128];

    int qb = blockIdx.x, bh = blockIdx.y;
    int t = threadIdx.x, w = t >> 5;             // 8 warps
    const float* qp = g_q + ((size_t)bh * HWN) * HD;
    const float* kp = g_k + ((size_t)bh * HWN) * HD;
    const float* vp = g_v + ((size_t)bh * HWN) * HD;
    int q0 = qb * 128;

    #pragma unroll
    for (int i = 0; i < 32; i++) {               // load Q tile, pre-scaled
        int e = i * 256 + t;
        int r = e >> 6, d = e & 63;
        Qs[r * 68 + d] = wmma::__float_to_tf32(qp[(size_t)(q0 + r) * HD + d] * 0.125f);
    }
    if (t < 128) den[t] = 0.f;

    wmma::fragment<wmma::accumulator, 16, 16, 8, float> oacc[4];
    #pragma unroll
    for (int j = 0; j < 4; j++) wmma::fill_fragment(oacc[j], 0.f);

    for (int kb = 0; kb < 64; kb++) {
        __syncthreads();                         // protect Ks/Vs/Ss reuse (and Q on iter 0)
        int k0 = kb * 64;
        #pragma unroll
        for (int i = 0; i < 16; i++) {
            int e = i * 256 + t;
            int r = e >> 6, d = e & 63;
            Ks[r * 68 + d] = wmma::__float_to_tf32(kp[(size_t)(k0 + r) * HD + d]);
            Vs[r * 68 + d] = wmma::__float_to_tf32(vp[(size_t)(k0 + r) * HD + d]);
        }
        __syncthreads();

        // S = Q K^T  (warp w: rows 16w..16w+15, all 64 key cols)
        wmma::fragment<wmma::accumulator, 16, 16, 8, float> sacc[4];
        #pragma unroll
        for (int j = 0; j < 4; j++) wmma::fill_fragment(sacc[j], 0.f);
        #pragma unroll
        for (int d0 = 0; d0 < 64; d0 += 8) {
            wmma::fragment<wmma::matrix_a, 16, 16, 8, wmma::precision::tf32, wmma::row_major> a;
            wmma::load_matrix_sync(a, Qs + (w * 16) * 68 + d0, 68);
            #pragma unroll
            for (int j = 0; j < 4; j++) {
                wmma::fragment<wmma::matrix_b, 16, 16, 8, wmma::precision::tf32, wmma::col_major> bb;
                wmma::load_matrix_sync(bb, Ks + (j * 16) * 68 + d0, 68);
                wmma::mma_sync(sacc[j], a, bb, sacc[j]);
            }
        }
        #pragma unroll
        for (int j = 0; j < 4; j++)
            wmma::store_matrix_sync(Ss + (w * 16) * 68 + j * 16, sacc[j], 68, wmma::mem_row_major);
        __syncthreads();

        // P = exp(S - 4); accumulate row denominators (2 threads / row)
        {
            int row = t >> 1;
            int cb  = (t & 1) * 32;
            float local = 0.f;
            #pragma unroll
            for (int c = 0; c < 32; c++) {
                int idx = row * 68 + cb + c;
                float p = fast_exp(Ss[idx] - 4.0f);
                p = wmma::__float_to_tf32(p);
                Ss[idx] = p;
                local += p;
            }
            local += __shfl_xor_sync(0xffffffffu, local, 1);
            if ((t & 1) == 0) den[row] += local;
        }
        __syncthreads();

        // O += P V
        #pragma unroll
        for (int k2 = 0; k2 < 64; k2 += 8) {
            wmma::fragment<wmma::matrix_a, 16, 16, 8, wmma::precision::tf32, wmma::row_major> a;
            wmma::load_matrix_sync(a, Ss + (w * 16) * 68 + k2, 68);
            #pragma unroll
            for (int j = 0; j < 4; j++) {
                wmma::fragment<wmma::matrix_b, 16, 16, 8, wmma::precision::tf32, wmma::row_major> bb;
                wmma::load_matrix_sync(bb, Vs + k2 * 68 + j * 16, 68);
                wmma::mma_sync(oacc[j], a, bb, oacc[j]);
            }
        }
    }
    __syncthreads();
    #pragma unroll
    for (int j = 0; j < 4; j++)
        wmma::store_matrix_sync(Ss + (w * 16) * 68 + j * 16, oacc[j], 68, wmma::mem_row_major);
    __syncthreads();

    int b = bh >> 2, h = bh & 3;
    #pragma unroll
    for (int i = 0; i < 32; i++) {
        int e = i * 256 + t;
        int r = e >> 6, d = e & 63;
        g_ao[((size_t)(b * HWN + q0 + r)) * CNUM + h * HD + d] = Ss[r * 68 + d] / den[r];
    }
}

// ---------------- kernel 4: proj GEMM + residual ---------------------------
__global__ __launch_bounds__(128) void proj_kernel(const float* __restrict__ x,
                                                   const float* __restrict__ wproj,
                                                   const float* __restrict__ bproj,
                                                   float* __restrict__ out) {
    __shared__ float sm[4608];
    float* As = sm;          // row-major: As[m*36 + k]
    float* Bs = sm + 2304;   // Bs[n*36 + k]
    int nt = blockIdx.x;     // 0..3
    int mt = blockIdx.y;     // 0..255
    int p0 = mt * 64;
    int b  = p0 >> 12;
    int hw0 = p0 & (HWN - 1);
    int o0 = nt * 64;
    int t = threadIdx.x, w = t >> 5;
    int wm = w & 1, wn = w >> 1;

    wmma::fragment<wmma::accumulator, 16, 16, 8, float> acc[2][2];
    #pragma unroll
    for (int i = 0; i < 2; i++)
        #pragma unroll
        for (int j = 0; j < 2; j++) wmma::fill_fragment(acc[i][j], 0.0f);

    for (int kt = 0; kt < 8; kt++) {
        int c0 = kt * 32;
        __syncthreads();
        #pragma unroll
        for (int i = 0; i < 16; i++) {
            int e = i * 128 + t;
            int k = e & 31, m = e >> 5;
            As[m * 36 + k] = wmma::__float_to_tf32(g_ao[((size_t)(p0 + m)) * CNUM + c0 + k]);
        }
        #pragma unroll
        for (int i = 0; i < 16; i++) {
            int e = i * 128 + t;
            int k = e & 31, n = e >> 5;
            Bs[n * 36 + k] = wmma::__float_to_tf32(wproj[(size_t)(o0 + n) * CNUM + c0 + k]);
        }
        __syncthreads();
        #pragma unroll
        for (int kk = 0; kk < 32; kk += 8) {
            wmma::fragment<wmma::matrix_a, 16, 16, 8, wmma::precision::tf32, wmma::row_major> a[2];
            wmma::fragment<wmma::matrix_b, 16, 16, 8, wmma::precision::tf32, wmma::col_major> bb[2];
            #pragma unroll
            for (int i = 0; i < 2; i++)
                wmma::load_matrix_sync(a[i], As + (wm * 32 + i * 16) * 36 + kk, 36);
            #pragma unroll
            for (int j = 0; j < 2; j++)
                wmma::load_matrix_sync(bb[j], Bs + (wn * 32 + j * 16) * 36 + kk, 36);
            #pragma unroll
            for (int i = 0; i < 2; i++)
                #pragma unroll
                for (int j = 0; j < 2; j++)
                    wmma::mma_sync(acc[i][j], a[i], bb[j], acc[i][j]);
        }
    }
    __syncthreads();
    float* Cs = sm;
    #pragma unroll
    for (int i = 0; i < 2; i++)
        #pragma unroll
        for (int j = 0; j < 2; j++)
            wmma::store_matrix_sync(Cs + (wm * 32 + i * 16) * 68 + (wn * 32 + j * 16),
                                    acc[i][j], 68, wmma::mem_row_major);
    __syncthreads();
    #pragma unroll
    for (int i = 0; i < 32; i++) {
        int e = i * 128 + t;
        int m = e & 63, n = e >> 6;
        size_t oidx = (((size_t)(b * CNUM + o0 + n)) << 12) + hw0 + m;
        out[oidx] = x[oidx] + Cs[m * 68 + n] + bproj[o0 + n];
    }
}

// ---------------- launch ----------------------------------------------------
extern "C" void kernel_launch(void* const* d_in, const int* in_sizes, int n_in,
                              void* d_out, int out_size) {
    const float* x      = (const float*)d_in[0];
    const float* gamma  = (const float*)d_in[1];
    const float* beta   = (const float*)d_in[2];
    const float* w_qkv  = (const float*)d_in[3];
    const float* b_qkv  = (const float*)d_in[4];
    const float* w_proj = (const float*)d_in[5];
    const float* b_proj = (const float*)d_in[6];
    float* out = (float*)d_out;

    gn_stats_kernel<<<32, 256>>>(x, gamma, beta);
    qkv_kernel<<<dim3(12, 256), 128>>>(x, w_qkv, b_qkv);

    const int attn_smem = 26112 * (int)sizeof(float);   // 104448 B
    cudaFuncSetAttribute(attn_kernel, cudaFuncAttributeMaxDynamicSharedMemorySize, attn_smem);
    attn_kernel<<<dim3(32, 16), 256, attn_smem>>>();

    proj_kernel<<<dim3(4, 256), 128>>>(x, w_proj, b_proj, out);
}

// round 2
// speedup vs baseline: 5.5748x; 5.5748x over previous
#include <cuda_runtime.h>
#include <cuda_bf16.h>
#include <mma.h>

using namespace nvcuda;

#define B_NUM 4
#define CNUM  256
#define HWN   4096
#define NH    4
#define HD    64
#define LOG2E 1.4426950408889634f
#define QSCALE (0.125f * LOG2E)
#define ATT_OFF 5.770780163555854f   // 4 * log2(e)

// ---------------- scratch (device globals; allocation-free rule) ----------
__device__ float g_scale[B_NUM * CNUM];
__device__ float g_bias [B_NUM * CNUM];
__device__ float g_part [512];
__device__ __nv_bfloat16 g_qb[B_NUM * NH * HWN * HD];
__device__ __nv_bfloat16 g_kb[B_NUM * NH * HWN * HD];
__device__ __nv_bfloat16 g_vb[B_NUM * NH * HWN * HD];
__device__ float g_ao[B_NUM * HWN * CNUM];   // attention out, [b*4096+pix][c]

// ---------------- small asm helpers ----------------------------------------
__device__ __forceinline__ unsigned s2u(const void* p) {
    unsigned a;
    asm("{ .reg .u64 t; cvta.to.shared.u64 t, %1; cvt.u32.u64 %0, t; }" : "=r"(a) : "l"(p));
    return a;
}
__device__ __forceinline__ void cpa16(unsigned d, const void* s) {
    asm volatile("cp.async.cg.shared.global [%0], [%1], 16;" :: "r"(d), "l"(s));
}
__device__ __forceinline__ void ldsm4(unsigned* r, unsigned a) {
    asm volatile("ldmatrix.sync.aligned.m8n8.x4.shared.b16 {%0,%1,%2,%3}, [%4];"
        : "=r"(r[0]), "=r"(r[1]), "=r"(r[2]), "=r"(r[3]) : "r"(a));
}
__device__ __forceinline__ void ldsm4t(unsigned* r, unsigned a) {
    asm volatile("ldmatrix.sync.aligned.m8n8.x4.trans.shared.b16 {%0,%1,%2,%3}, [%4];"
        : "=r"(r[0]), "=r"(r[1]), "=r"(r[2]), "=r"(r[3]) : "r"(a));
}
__device__ __forceinline__ void mma_bf(float* c, const unsigned* a, unsigned b0, unsigned b1) {
    asm volatile("mma.sync.aligned.m16n8k16.row.col.f32.bf16.bf16.f32 "
        "{%0,%1,%2,%3}, {%4,%5,%6,%7}, {%8,%9}, {%0,%1,%2,%3};"
        : "+f"(c[0]), "+f"(c[1]), "+f"(c[2]), "+f"(c[3])
        : "r"(a[0]), "r"(a[1]), "r"(a[2]), "r"(a[3]), "r"(b0), "r"(b1));
}
__device__ __forceinline__ float ex2f(float x) {
    float r; asm("ex2.approx.f32 %0, %1;" : "=f"(r) : "f"(x)); return r;
}
__device__ __forceinline__ unsigned packbf(float lo, float hi) {
    unsigned r; asm("cvt.rn.bf16x2.f32 %0, %1, %2;" : "=r"(r) : "f"(hi), "f"(lo)); return r;
}

// ---------------- kernel 1a: groupnorm partial sums ------------------------
__global__ void gn_partial(const float* __restrict__ x) {
    int blk = blockIdx.x;                         // bg*8 + slice, 256 blocks
    const float4* base = (const float4*)x + (size_t)blk * 4096;
    float s = 0.f, s2 = 0.f;
    for (int i = threadIdx.x; i < 4096; i += 256) {
        float4 v = base[i];
        s  += (v.x + v.y) + (v.z + v.w);
        s2 += (v.x*v.x + v.y*v.y) + (v.z*v.z + v.w*v.w);
    }
    __shared__ float r1[256], r2[256];
    r1[threadIdx.x] = s; r2[threadIdx.x] = s2;
    __syncthreads();
    for (int off = 128; off > 0; off >>= 1) {
        if (threadIdx.x < off) {
            r1[threadIdx.x] += r1[threadIdx.x + off];
            r2[threadIdx.x] += r2[threadIdx.x + off];
        }
        __syncthreads();
    }
    if (threadIdx.x == 0) { g_part[blk*2] = r1[0]; g_part[blk*2+1] = r2[0]; }
}

// ---------------- kernel 1b: finalize scale/bias ----------------------------
__global__ void gn_final(const float* __restrict__ gamma, const float* __restrict__ beta) {
    __shared__ float mean_s[32], rstd_s[32];
    int t = threadIdx.x;
    if (t < 32) {
        float s = 0.f, s2 = 0.f;
        #pragma unroll
        for (int i = 0; i < 8; i++) { s += g_part[(t*8+i)*2]; s2 += g_part[(t*8+i)*2+1]; }
        float mean = s * (1.f/131072.f);
        float var  = s2 * (1.f/131072.f) - mean*mean;
        mean_s[t] = mean;
        rstd_s[t] = rsqrtf(var + 1e-5f);
    }
    __syncthreads();
    for (int idx = t; idx < 1024; idx += 256) {
        int b = idx >> 8, c = idx & 255;
        int bg = b*8 + (c >> 5);
        float sc = rstd_s[bg] * gamma[c];
        g_scale[idx] = sc;
        g_bias [idx] = beta[c] - mean_s[bg] * sc;
    }
}

// ---------------- kernel 2: fused GN + QKV GEMM (bf16 wmma) ----------------
__global__ __launch_bounds__(128) void qkv_kernel(const float* __restrict__ x,
                                                  const float* __restrict__ wqkv,
                                                  const float* __restrict__ bqkv) {
    __shared__ __nv_bfloat16 As[32*72];   // [k][m]  (A col-major)
    __shared__ __nv_bfloat16 Bs[64*40];   // [n][k]  (B col-major k x n)
    __shared__ float Cs[64*68];
    int nt = blockIdx.x, mt = blockIdx.y;
    int p0 = mt * 64;
    int b  = p0 >> 12;
    int hw0 = p0 & (HWN - 1);
    int o0 = nt * 64;
    int t = threadIdx.x, w = t >> 5, wm = w & 1, wn = w >> 1;

    wmma::fragment<wmma::accumulator, 16, 16, 16, float> acc[2][2];
    #pragma unroll
    for (int i = 0; i < 2; i++)
        #pragma unroll
        for (int j = 0; j < 2; j++) wmma::fill_fragment(acc[i][j], 0.0f);

    for (int kt = 0; kt < 8; kt++) {
        int c0 = kt * 32;
        __syncthreads();
        #pragma unroll
        for (int i = 0; i < 16; i++) {               // A: 64m x 32k (GN applied)
            int e = i * 128 + t;
            int m = e & 63, k = e >> 6;
            int c = c0 + k;
            float v = fmaf(x[(((size_t)(b * CNUM + c)) << 12) + hw0 + m],
                           g_scale[b * CNUM + c], g_bias[b * CNUM + c]);
            As[k * 72 + m] = __float2bfloat16(v);
        }
        #pragma unroll
        for (int i = 0; i < 16; i++) {               // B: 64n x 32k
            int e = i * 128 + t;
            int k = e & 31, n = e >> 5;
            Bs[n * 40 + k] = __float2bfloat16(wqkv[(size_t)(o0 + n) * CNUM + c0 + k]);
        }
        __syncthreads();
        #pragma unroll
        for (int kk = 0; kk < 32; kk += 16) {
            wmma::fragment<wmma::matrix_a, 16, 16, 16, __nv_bfloat16, wmma::col_major> a[2];
            wmma::fragment<wmma::matrix_b, 16, 16, 16, __nv_bfloat16, wmma::col_major> bb[2];
            #pragma unroll
            for (int i = 0; i < 2; i++)
                wmma::load_matrix_sync(a[i], As + kk * 72 + (wm * 32 + i * 16), 72);
            #pragma unroll
            for (int j = 0; j < 2; j++)
                wmma::load_matrix_sync(bb[j], Bs + (wn * 32 + j * 16) * 40 + kk, 40);
            #pragma unroll
            for (int i = 0; i < 2; i++)
                #pragma unroll
                for (int j = 0; j < 2; j++)
                    wmma::mma_sync(acc[i][j], a[i], bb[j], acc[i][j]);
        }
    }
    __syncthreads();
    #pragma unroll
    for (int i = 0; i < 2; i++)
        #pragma unroll
        for (int j = 0; j < 2; j++)
            wmma::store_matrix_sync(Cs + (wm * 32 + i * 16) * 68 + (wn * 32 + j * 16),
                                    acc[i][j], 68, wmma::mem_row_major);
    __syncthreads();
    int which = o0 >> 8;                // 0=q,1=k,2=v
    int head  = (o0 >> 6) & 3;
    __nv_bfloat16* dst = (which == 0) ? g_qb : (which == 1) ? g_kb : g_vb;
    float mul = (which == 0) ? QSCALE : 1.0f;
    #pragma unroll
    for (int i = 0; i < 32; i++) {
        int e = i * 128 + t;
        int n = e & 63, m = e >> 6;
        float v = (Cs[m * 68 + n] + bqkv[o0 + n]) * mul;
        dst[(((size_t)((b * NH + head) * HWN + hw0 + m)) << 6) + n] = __float2bfloat16(v);
    }
}

// ---------------- kernel 3: attention (FA2-style, raw mma, bf16) -----------
// grid (32, 16): 128-query tiles x batch-heads. 128 threads = 4 warps x 32 rows.
__global__ __launch_bounds__(128, 2) void attn_kernel() {
    extern __shared__ __align__(16) char dsm[];
    const int SP = 72;                              // padded bf16 row stride
    int t = threadIdx.x;
    int w = t >> 5, l = t & 31;
    int qb = blockIdx.x, bh = blockIdx.y;
    int q0 = qb * 128;
    const __nv_bfloat16* qp = g_qb + (size_t)bh * HWN * HD + (size_t)q0 * HD;
    const __nv_bfloat16* kp = g_kb + (size_t)bh * HWN * HD;
    const __nv_bfloat16* vp = g_vb + (size_t)bh * HWN * HD;

    unsigned su = s2u(dsm);
    unsigned Qs = su;
    unsigned KB0 = su + 128 * SP * 2;
    unsigned KB1 = KB0 + 64 * SP * 2;
    unsigned VB0 = KB1 + 64 * SP * 2;
    unsigned VB1 = VB0 + 64 * SP * 2;

    // prefetch K/V block 0
    {
        #pragma unroll
        for (int i = 0; i < 4; i++) {
            int c = i * 128 + t;
            int row = c >> 3, col8 = c & 7;
            unsigned so = (unsigned)(row * SP + col8 * 8) * 2;
            cpa16(KB0 + so, kp + (size_t)row * 64 + col8 * 8);
            cpa16(VB0 + so, vp + (size_t)row * 64 + col8 * 8);
        }
        asm volatile("cp.async.commit_group;" ::: "memory");
    }
    // Q tile -> smem (16B copies)
    #pragma unroll
    for (int i = 0; i < 8; i++) {
        int c = i * 128 + t;
        int row = c >> 3, col8 = c & 7;
        *(uint4*)(dsm + (size_t)(row * SP + col8 * 8) * 2) =
            *(const uint4*)(qp + (size_t)row * 64 + col8 * 8);
    }
    __syncthreads();

    int lrow_a = l & 15,  lcol_a = (l >> 4) * 8;               // A / V-trans pattern
    int lrow_k = (l & 7) + ((l >> 4) << 3), lcol_k = ((l >> 3) & 1) * 8;  // K pattern
    int r0 = w * 32;

    unsigned qf[2][4][4];
    #pragma unroll
    for (int mb = 0; mb < 2; mb++)
        #pragma unroll
        for (int kc = 0; kc < 4; kc++)
            ldsm4(qf[mb][kc],
                  Qs + (unsigned)(((r0 + mb*16 + lrow_a) * SP + kc*16 + lcol_a) * 2));

    float oacc[2][8][4];
    #pragma unroll
    for (int mb = 0; mb < 2; mb++)
        #pragma unroll
        for (int j = 0; j < 8; j++)
            #pragma unroll
            for (int i = 0; i < 4; i++) oacc[mb][j][i] = 0.f;
    float rs[4] = {0.f, 0.f, 0.f, 0.f};

    for (int kb = 0; kb < 64; kb++) {
        asm volatile("cp.async.wait_group 0;" ::: "memory");
        __syncthreads();
        if (kb + 1 < 64) {
            int k0 = (kb + 1) * 64;
            unsigned kd = ((kb + 1) & 1) ? KB1 : KB0;
            unsigned vd = ((kb + 1) & 1) ? VB1 : VB0;
            #pragma unroll
            for (int i = 0; i < 4; i++) {
                int c = i * 128 + t;
                int row = c >> 3, col8 = c & 7;
                unsigned so = (unsigned)(row * SP + col8 * 8) * 2;
                cpa16(kd + so, kp + (size_t)(k0 + row) * 64 + col8 * 8);
                cpa16(vd + so, vp + (size_t)(k0 + row) * 64 + col8 * 8);
            }
            asm volatile("cp.async.commit_group;" ::: "memory");
        }
        unsigned kS = (kb & 1) ? KB1 : KB0;
        unsigned vS = (kb & 1) ? VB1 : VB0;

        unsigned pf[2][4][4];
        #pragma unroll
        for (int g = 0; g < 4; g++) {
            float s0[2][4] = {{0.f,0.f,0.f,0.f},{0.f,0.f,0.f,0.f}};
            float s1[2][4] = {{0.f,0.f,0.f,0.f},{0.f,0.f,0.f,0.f}};
            #pragma unroll
            for (int kc = 0; kc < 4; kc++) {
                unsigned bb[4];
                ldsm4(bb, kS + (unsigned)(((g*16 + lrow_k) * SP + kc*16 + lcol_k) * 2));
                mma_bf(s0[0], qf[0][kc], bb[0], bb[1]);
                mma_bf(s1[0], qf[0][kc], bb[2], bb[3]);
                mma_bf(s0[1], qf[1][kc], bb[0], bb[1]);
                mma_bf(s1[1], qf[1][kc], bb[2], bb[3]);
            }
            #pragma unroll
            for (int mb = 0; mb < 2; mb++) {
                float e0 = ex2f(s0[mb][0] - ATT_OFF), e1 = ex2f(s0[mb][1] - ATT_OFF);
                float e2 = ex2f(s0[mb][2] - ATT_OFF), e3 = ex2f(s0[mb][3] - ATT_OFF);
                float f0 = ex2f(s1[mb][0] - ATT_OFF), f1 = ex2f(s1[mb][1] - ATT_OFF);
                float f2 = ex2f(s1[mb][2] - ATT_OFF), f3 = ex2f(s1[mb][3] - ATT_OFF);
                rs[mb*2+0] += (e0 + e1) + (f0 + f1);
                rs[mb*2+1] += (e2 + e3) + (f2 + f3);
                pf[mb][g][0] = packbf(e0, e1);
                pf[mb][g][1] = packbf(e2, e3);
                pf[mb][g][2] = packbf(f0, f1);
                pf[mb][g][3] = packbf(f2, f3);
            }
        }
        #pragma unroll
        for (int g = 0; g < 4; g++) {
            #pragma unroll
            for (int dg = 0; dg < 4; dg++) {
                unsigned vv[4];
                ldsm4t(vv, vS + (unsigned)(((g*16 + lrow_a) * SP + dg*16 + lcol_a) * 2));
                mma_bf(oacc[0][2*dg],   pf[0][g], vv[0], vv[1]);
                mma_bf(oacc[0][2*dg+1], pf[0][g], vv[2], vv[3]);
                mma_bf(oacc[1][2*dg],   pf[1][g], vv[0], vv[1]);
                mma_bf(oacc[1][2*dg+1], pf[1][g], vv[2], vv[3]);
            }
        }
    }

    #pragma unroll
    for (int i = 0; i < 4; i++) {
        rs[i] += __shfl_xor_sync(0xffffffffu, rs[i], 1);
        rs[i] += __shfl_xor_sync(0xffffffffu, rs[i], 2);
    }
    int b = bh >> 2, h = bh & 3;
    float* aop = g_ao + ((size_t)b * HWN + q0) * CNUM + h * HD;
    #pragma unroll
    for (int mb = 0; mb < 2; mb++) {
        float i0 = 1.0f / rs[mb*2], i1 = 1.0f / rs[mb*2+1];
        int row0 = r0 + mb*16 + (l >> 2);
        int cbase = (l & 3) * 2;
        #pragma unroll
        for (int j = 0; j < 8; j++) {
            float2 u; u.x = oacc[mb][j][0] * i0; u.y = oacc[mb][j][1] * i0;
            *(float2*)(aop + (size_t)row0 * CNUM + j*8 + cbase) = u;
            float2 v; v.x = oacc[mb][j][2] * i1; v.y = oacc[mb][j][3] * i1;
            *(float2*)(aop + (size_t)(row0 + 8) * CNUM + j*8 + cbase) = v;
        }
    }
}

// ---------------- kernel 4: proj GEMM + residual (bf16 wmma) ---------------
__global__ __launch_bounds__(128) void proj_kernel(const float* __restrict__ x,
                                                   const float* __restrict__ wproj,
                                                   const float* __restrict__ bproj,
                                                   float* __restrict__ out) {
    __shared__ __nv_bfloat16 As[64*40];   // [m][k] row-major
    __shared__ __nv_bfloat16 Bs[64*40];   // [n][k]
    __shared__ float Cs[64*68];
    int nt = blockIdx.x, mt = blockIdx.y;
    int p0 = mt * 64;
    int b  = p0 >> 12;
    int hw0 = p0 & (HWN - 1);
    int o0 = nt * 64;
    int t = threadIdx.x, w = t >> 5, wm = w & 1, wn = w >> 1;

    wmma::fragment<wmma::accumulator, 16, 16, 16, float> acc[2][2];
    #pragma unroll
    for (int i = 0; i < 2; i++)
        #pragma unroll
        for (int j = 0; j < 2; j++) wmma::fill_fragment(acc[i][j], 0.0f);

    for (int kt = 0; kt < 8; kt++) {
        int c0 = kt * 32;
        __syncthreads();
        #pragma unroll
        for (int i = 0; i < 16; i++) {
            int e = i * 128 + t;
            int k = e & 31, m = e >> 5;
            As[m * 40 + k] = __float2bfloat16(g_ao[((size_t)(p0 + m)) * CNUM + c0 + k]);
        }
        #pragma unroll
        for (int i = 0; i < 16; i++) {
            int e = i * 128 + t;
            int k = e & 31, n = e >> 5;
            Bs[n * 40 + k] = __float2bfloat16(wproj[(size_t)(o0 + n) * CNUM + c0 + k]);
        }
        __syncthreads();
        #pragma unroll
        for (int kk = 0; kk < 32; kk += 16) {
            wmma::fragment<wmma::matrix_a, 16, 16, 16, __nv_bfloat16, wmma::row_major> a[2];
            wmma::fragment<wmma::matrix_b, 16, 16, 16, __nv_bfloat16, wmma::col_major> bb[2];
            #pragma unroll
            for (int i = 0; i < 2; i++)
                wmma::load_matrix_sync(a[i], As + (wm * 32 + i * 16) * 40 + kk, 40);
            #pragma unroll
            for (int j = 0; j < 2; j++)
                wmma::load_matrix_sync(bb[j], Bs + (wn * 32 + j * 16) * 40 + kk, 40);
            #pragma unroll
            for (int i = 0; i < 2; i++)
                #pragma unroll
                for (int j = 0; j < 2; j++)
                    wmma::mma_sync(acc[i][j], a[i], bb[j], acc[i][j]);
        }
    }
    __syncthreads();
    #pragma unroll
    for (int i = 0; i < 2; i++)
        #pragma unroll
        for (int j = 0; j < 2; j++)
            wmma::store_matrix_sync(Cs + (wm * 32 + i * 16) * 68 + (wn * 32 + j * 16),
                                    acc[i][j], 68, wmma::mem_row_major);
    __syncthreads();
    #pragma unroll
    for (int i = 0; i < 32; i++) {
        int e = i * 128 + t;
        int m = e & 63, n = e >> 6;
        size_t oidx = (((size_t)(b * CNUM + o0 + n)) << 12) + hw0 + m;
        out[oidx] = x[oidx] + Cs[m * 68 + n] + bproj[o0 + n];
    }
}

// ---------------- launch ----------------------------------------------------
extern "C" void kernel_launch(void* const* d_in, const int* in_sizes, int n_in,
                              void* d_out, int out_size) {
    const float* x      = (const float*)d_in[0];
    const float* gamma  = (const float*)d_in[1];
    const float* beta   = (const float*)d_in[2];
    const float* w_qkv  = (const float*)d_in[3];
    const float* b_qkv  = (const float*)d_in[4];
    const float* w_proj = (const float*)d_in[5];
    const float* b_proj = (const float*)d_in[6];
    float* out = (float*)d_out;

    gn_partial<<<256, 256>>>(x);
    gn_final<<<1, 256>>>(gamma, beta);
    qkv_kernel<<<dim3(12, 256), 128>>>(x, w_qkv, b_qkv);

    const int attn_smem = (128 + 4 * 64) * 72 * 2;   // 55296 B
    cudaFuncSetAttribute(attn_kernel, cudaFuncAttributeMaxDynamicSharedMemorySize, attn_smem);
    attn_kernel<<<dim3(32, 16), 128, attn_smem>>>();

    proj_kernel<<<dim3(4, 256), 128>>>(x, w_proj, b_proj, out);
}